// round 2
// baseline (speedup 1.0000x reference)
#include <cuda_runtime.h>

// Window attention, fully fused: one CTA per window (2048 CTAs, 256 threads).
// fp32 SIMT baseline with register-tiled GEMMs and all intermediates in SMEM.

#define NTOK 64
#define DIM  192
#define NH   6
#define HD   32
#define SXS  196              // padded row stride (floats): 16B-aligned, not mult of 32
#define BUF  (NTOK * SXS)     // 12544 floats per 64x192 buffer

__device__ __forceinline__ float getc(float4 v, int u) {
    return u == 0 ? v.x : u == 1 ? v.y : u == 2 ? v.z : v.w;
}

__global__ __launch_bounds__(256, 1)
void win_attn_kernel(const float* __restrict__ x,
                     const float* __restrict__ mask,
                     const float* __restrict__ w_qkv,
                     const float* __restrict__ b_qkv,
                     const float* __restrict__ rpbt,
                     const float* __restrict__ w_proj,
                     const float* __restrict__ b_proj,
                     float* __restrict__ out)
{
    extern __shared__ float sm[];
    float* sx = sm;               // 64x192 input, later reused as attention output
    float* sq = sm + BUF;
    float* sk = sm + 2 * BUF;
    float* sv = sm + 3 * BUF;
    float* ws = sm + 4 * BUF;     // 16x192 weight tile

    const int tid = threadIdx.x;
    const int b   = blockIdx.x;
    const int tx  = tid & 15;     // 16 col-groups of 12
    const int ty  = tid >> 4;     // 16 row-groups of 4

    const float SCALE = 0.17677669529663689f;  // 32^-0.5
    const float LOG2E = 1.4426950408889634f;

    // ---------------- Phase 1: load x (64x192) into SMEM ----------------
    {
        const float* xg = x + (size_t)b * (NTOK * DIM);
        #pragma unroll
        for (int i = 0; i < 12; ++i) {
            int f  = tid + i * 256;        // 3072 float4 total
            int r  = f / 48;
            int c4 = f % 48;
            *(float4*)&sx[r * SXS + c4 * 4] = *(const float4*)&xg[r * DIM + c4 * 4];
        }
    }
    // (ordered by the first __syncthreads inside the tile loop below)

    // ---------------- Phase 2: qkv = x @ w_qkv + b_qkv ----------------
    // w_qkv is [192][576]; columns split as (m=0..2)*192 + h*32 + d.
    #pragma unroll 1
    for (int m = 0; m < 3; ++m) {
        float acc[4][12];
        #pragma unroll
        for (int i = 0; i < 4; ++i)
            #pragma unroll
            for (int c = 0; c < 12; ++c) acc[i][c] = 0.f;

        #pragma unroll 1
        for (int k0 = 0; k0 < DIM; k0 += 16) {
            __syncthreads();
            #pragma unroll
            for (int i = 0; i < 3; ++i) {
                int f  = tid + i * 256;    // 768 float4
                int kk = f / 48;
                int c4 = f % 48;
                *(float4*)&ws[kk * 192 + c4 * 4] =
                    *(const float4*)&w_qkv[(k0 + kk) * 576 + m * 192 + c4 * 4];
            }
            __syncthreads();

            #pragma unroll
            for (int kq = 0; kq < 4; ++kq) {
                float4 a4[4];
                #pragma unroll
                for (int i = 0; i < 4; ++i)
                    a4[i] = *(const float4*)&sx[(ty * 4 + i) * SXS + k0 + kq * 4];
                #pragma unroll
                for (int u = 0; u < 4; ++u) {
                    int kk = kq * 4 + u;
                    float4 b4[3];
                    #pragma unroll
                    for (int c = 0; c < 3; ++c)
                        b4[c] = *(const float4*)&ws[kk * 192 + tx * 12 + c * 4];
                    #pragma unroll
                    for (int i = 0; i < 4; ++i) {
                        float av = getc(a4[i], u);
                        #pragma unroll
                        for (int c = 0; c < 12; ++c)
                            acc[i][c] = fmaf(av, getc(b4[c >> 2], c & 3), acc[i][c]);
                    }
                }
            }
        }

        float* dst = (m == 0) ? sq : (m == 1) ? sk : sv;
        float scl  = (m == 0) ? SCALE : 1.0f;
        #pragma unroll
        for (int i = 0; i < 4; ++i)
            #pragma unroll
            for (int c = 0; c < 12; ++c) {
                int col = tx * 12 + c;
                dst[(ty * 4 + i) * SXS + col] =
                    (acc[i][c] + __ldg(&b_qkv[m * 192 + col])) * scl;
            }
    }
    __syncthreads();

    // ---------------- Phase 3: attention (per head,row in registers) -------
    {
        const int wwin = b & 63;   // mask window index
        #pragma unroll 1
        for (int g = tid; g < NTOK * NH; g += 256) {
            const int head = g >> 6;
            const int row  = g & 63;

            float4 q4[8];
            {
                const float4* qr = (const float4*)(sq + row * SXS + head * HD);
                #pragma unroll
                for (int u = 0; u < 8; ++u) q4[u] = qr[u];
            }

            float att[NTOK];
            #pragma unroll
            for (int j = 0; j < NTOK; ++j) {
                const float4* kr = (const float4*)(sk + j * SXS + head * HD);
                float s = 0.f;
                #pragma unroll
                for (int u = 0; u < 8; ++u) {
                    float4 kv = kr[u];
                    s = fmaf(q4[u].x, kv.x, s);
                    s = fmaf(q4[u].y, kv.y, s);
                    s = fmaf(q4[u].z, kv.z, s);
                    s = fmaf(q4[u].w, kv.w, s);
                }
                att[j] = s;
            }

            // relative position bias + attention mask
            {
                const float* mrow = mask + ((size_t)wwin * NTOK + row) * NTOK;
                const int rh = row >> 3, rw = row & 7;
                #pragma unroll
                for (int j = 0; j < NTOK; ++j) {
                    int idx = (rh - (j >> 3) + 7) * 15 + (rw - (j & 7) + 7);
                    att[j] += __ldg(&rpbt[idx * NH + head]) + __ldg(&mrow[j]);
                }
            }

            // softmax
            float mx = -1e30f;
            #pragma unroll
            for (int j = 0; j < NTOK; ++j) mx = fmaxf(mx, att[j]);
            float sum = 0.f;
            #pragma unroll
            for (int j = 0; j < NTOK; ++j) {
                att[j] = exp2f((att[j] - mx) * LOG2E);
                sum += att[j];
            }
            const float inv = 1.f / sum;

            // att @ v
            float4 o[8];
            #pragma unroll
            for (int u = 0; u < 8; ++u) o[u] = make_float4(0.f, 0.f, 0.f, 0.f);
            #pragma unroll
            for (int j = 0; j < NTOK; ++j) {
                float p = att[j];
                const float4* vr = (const float4*)(sv + j * SXS + head * HD);
                #pragma unroll
                for (int u = 0; u < 8; ++u) {
                    float4 vv = vr[u];
                    o[u].x = fmaf(p, vv.x, o[u].x);
                    o[u].y = fmaf(p, vv.y, o[u].y);
                    o[u].z = fmaf(p, vv.z, o[u].z);
                    o[u].w = fmaf(p, vv.w, o[u].w);
                }
            }

            float4* dst = (float4*)(sx + row * SXS + head * HD);  // reuse sx
            #pragma unroll
            for (int u = 0; u < 8; ++u) {
                float4 ov = make_float4(o[u].x * inv, o[u].y * inv,
                                        o[u].z * inv, o[u].w * inv);
                dst[u] = ov;
            }
        }
    }
    __syncthreads();

    // ---------------- Phase 4: out = x_att @ w_proj + b_proj ----------------
    {
        float acc[4][12];
        #pragma unroll
        for (int i = 0; i < 4; ++i)
            #pragma unroll
            for (int c = 0; c < 12; ++c) acc[i][c] = 0.f;

        #pragma unroll 1
        for (int k0 = 0; k0 < DIM; k0 += 16) {
            __syncthreads();
            #pragma unroll
            for (int i = 0; i < 3; ++i) {
                int f  = tid + i * 256;
                int kk = f / 48;
                int c4 = f % 48;
                *(float4*)&ws[kk * 192 + c4 * 4] =
                    *(const float4*)&w_proj[(k0 + kk) * 192 + c4 * 4];
            }
            __syncthreads();

            #pragma unroll
            for (int kq = 0; kq < 4; ++kq) {
                float4 a4[4];
                #pragma unroll
                for (int i = 0; i < 4; ++i)
                    a4[i] = *(const float4*)&sx[(ty * 4 + i) * SXS + k0 + kq * 4];
                #pragma unroll
                for (int u = 0; u < 4; ++u) {
                    int kk = kq * 4 + u;
                    float4 b4[3];
                    #pragma unroll
                    for (int c = 0; c < 3; ++c)
                        b4[c] = *(const float4*)&ws[kk * 192 + tx * 12 + c * 4];
                    #pragma unroll
                    for (int i = 0; i < 4; ++i) {
                        float av = getc(a4[i], u);
                        #pragma unroll
                        for (int c = 0; c < 12; ++c)
                            acc[i][c] = fmaf(av, getc(b4[c >> 2], c & 3), acc[i][c]);
                    }
                }
            }
        }

        float* og = out + (size_t)b * (NTOK * DIM);
        #pragma unroll
        for (int i = 0; i < 4; ++i) {
            #pragma unroll
            for (int c4 = 0; c4 < 3; ++c4) {
                int col = tx * 12 + c4 * 4;
                float4 v;
                v.x = acc[i][c4 * 4 + 0] + __ldg(&b_proj[col + 0]);
                v.y = acc[i][c4 * 4 + 1] + __ldg(&b_proj[col + 1]);
                v.z = acc[i][c4 * 4 + 2] + __ldg(&b_proj[col + 2]);
                v.w = acc[i][c4 * 4 + 3] + __ldg(&b_proj[col + 3]);
                *(float4*)&og[(ty * 4 + i) * DIM + col] = v;
            }
        }
    }
}

extern "C" void kernel_launch(void* const* d_in, const int* in_sizes, int n_in,
                              void* d_out, int out_size)
{
    const float* x      = (const float*)d_in[0];
    const float* mask   = (const float*)d_in[1];
    const float* w_qkv  = (const float*)d_in[2];
    const float* b_qkv  = (const float*)d_in[3];
    const float* rpbt   = (const float*)d_in[4];
    const float* w_proj = (const float*)d_in[5];
    const float* b_proj = (const float*)d_in[6];
    float* out = (float*)d_out;

    const int smem_bytes = (4 * BUF + 16 * 192) * (int)sizeof(float);  // ~208 KB
    cudaFuncSetAttribute(win_attn_kernel,
                         cudaFuncAttributeMaxDynamicSharedMemorySize, smem_bytes);

    win_attn_kernel<<<2048, 256, smem_bytes>>>(x, mask, w_qkv, b_qkv,
                                               rpbt, w_proj, b_proj, out);
}